// round 1
// baseline (speedup 1.0000x reference)
#include <cuda_runtime.h>
#include <cuda_bf16.h>

#define BATCH  8
#define SLEN   1500
#define NSTATE 1024
#define NHEAD  16
#define HDIM   64
#define MROWS  (BATCH * SLEN)   // 12000

// ---------------- scratch (static device globals; no allocation) -------------
__device__ float g_Q[(size_t)MROWS * NSTATE];
__device__ float g_K[(size_t)MROWS * NSTATE];
__device__ float g_V[(size_t)MROWS * NSTATE];
__device__ float g_O[(size_t)MROWS * NSTATE];

// ---------------- GEMM: C[M,N] = A[M,K] @ W[N,K]^T + bias --------------------
// K = N = NSTATE = 1024 fixed. A row-major [M,1024], W row-major [1024,1024].
#define BM 128
#define BN 128
#define BK 16

__global__ __launch_bounds__(256) void gemm_bias_kernel(
    const float* __restrict__ A, const float* __restrict__ W,
    const float* __restrict__ bias, float* __restrict__ C, int M)
{
    __shared__ __align__(16) float As[BK][BM + 4];   // [k][m], stride 132 (16B multiple)
    __shared__ __align__(16) float Ws[BK][BN + 4];   // [k][n]

    const int tid = threadIdx.x;
    const int m0 = blockIdx.y * BM;
    const int n0 = blockIdx.x * BN;
    const int tx = tid & 15;        // 0..15  -> 8 output cols
    const int ty = tid >> 4;        // 0..15  -> 8 output rows

    const int lr = tid >> 2;        // 0..63 loader row
    const int lc = (tid & 3) * 4;   // 0,4,8,12 loader k-col

    float acc[8][8];
#pragma unroll
    for (int i = 0; i < 8; i++)
#pragma unroll
        for (int j = 0; j < 8; j++) acc[i][j] = 0.f;

    for (int k0 = 0; k0 < NSTATE; k0 += BK) {
        // load A tile [BM][BK] -> As[k][m]
#pragma unroll
        for (int rr = 0; rr < 2; rr++) {
            const int r  = lr + rr * 64;
            const int gm = m0 + r;
            float4 v = make_float4(0.f, 0.f, 0.f, 0.f);
            if (gm < M) v = *(const float4*)(A + (size_t)gm * NSTATE + k0 + lc);
            As[lc + 0][r] = v.x; As[lc + 1][r] = v.y;
            As[lc + 2][r] = v.z; As[lc + 3][r] = v.w;
        }
        // load W tile [BN][BK] -> Ws[k][n]   (N = 1024, always in range)
#pragma unroll
        for (int rr = 0; rr < 2; rr++) {
            const int r  = lr + rr * 64;
            const int gn = n0 + r;
            float4 v = *(const float4*)(W + (size_t)gn * NSTATE + k0 + lc);
            Ws[lc + 0][r] = v.x; Ws[lc + 1][r] = v.y;
            Ws[lc + 2][r] = v.z; Ws[lc + 3][r] = v.w;
        }
        __syncthreads();

#pragma unroll
        for (int kk = 0; kk < BK; kk++) {
            float a[8], b[8];
            float4 t0 = *(const float4*)&As[kk][ty * 8];
            float4 t1 = *(const float4*)&As[kk][ty * 8 + 4];
            a[0] = t0.x; a[1] = t0.y; a[2] = t0.z; a[3] = t0.w;
            a[4] = t1.x; a[5] = t1.y; a[6] = t1.z; a[7] = t1.w;
            float4 u0 = *(const float4*)&Ws[kk][tx * 8];
            float4 u1 = *(const float4*)&Ws[kk][tx * 8 + 4];
            b[0] = u0.x; b[1] = u0.y; b[2] = u0.z; b[3] = u0.w;
            b[4] = u1.x; b[5] = u1.y; b[6] = u1.z; b[7] = u1.w;
#pragma unroll
            for (int i = 0; i < 8; i++)
#pragma unroll
                for (int j = 0; j < 8; j++)
                    acc[i][j] = fmaf(a[i], b[j], acc[i][j]);
        }
        __syncthreads();
    }

    // epilogue: + bias, store
#pragma unroll
    for (int i = 0; i < 8; i++) {
        const int gm = m0 + ty * 8 + i;
        if (gm < M) {
#pragma unroll
            for (int jj = 0; jj < 2; jj++) {
                const int gn = n0 + tx * 8 + jj * 4;
                float4 o;
                o.x = acc[i][jj * 4 + 0] + (bias ? bias[gn + 0] : 0.f);
                o.y = acc[i][jj * 4 + 1] + (bias ? bias[gn + 1] : 0.f);
                o.z = acc[i][jj * 4 + 2] + (bias ? bias[gn + 2] : 0.f);
                o.w = acc[i][jj * 4 + 3] + (bias ? bias[gn + 3] : 0.f);
                *(float4*)(C + (size_t)gm * NSTATE + gn) = o;
            }
        }
    }
}

// ---------------- Flash attention (causal, fp32) -----------------------------
#define BQ    128
#define BKV   64
#define QPAD  68        // 68 floats = 272B: float4-aligned rows, conflict-free
#define SMEM_BYTES ((BQ + 2 * BKV) * QPAD * 4)   // 69632

__global__ __launch_bounds__(128) void flash_attn_kernel(
    const float* __restrict__ Q, const float* __restrict__ K,
    const float* __restrict__ V, float* __restrict__ O)
{
    extern __shared__ __align__(16) float smem[];
    float* Qs = smem;                       // [BQ][QPAD]
    float* Ks = smem + BQ * QPAD;           // [BKV][QPAD]
    float* Vs = Ks + BKV * QPAD;            // [BKV][QPAD]

    const int tid = threadIdx.x;
    const int bh  = blockIdx.y;
    const int b   = bh >> 4;
    const int h   = bh & 15;
    const int q0  = blockIdx.x * BQ;
    const int row = q0 + tid;
    const size_t baseRow = (size_t)b * SLEN;
    const int colOff = h * HDIM;

    // cooperative Q tile load (zero-fill past S)
#pragma unroll
    for (int it = 0; it < 16; it++) {
        const int f  = tid + it * 128;       // float4 index 0..2047
        const int r  = f >> 4;
        const int c4 = f & 15;
        const int gr = q0 + r;
        float4 v = make_float4(0.f, 0.f, 0.f, 0.f);
        if (gr < SLEN)
            v = *(const float4*)(Q + (baseRow + gr) * NSTATE + colOff + c4 * 4);
        *(float4*)&Qs[r * QPAD + c4 * 4] = v;
    }

    float m = -1e30f, l = 0.f;
    float acc[HDIM];
#pragma unroll
    for (int d = 0; d < HDIM; d++) acc[d] = 0.f;

    const int lastQ = min(q0 + BQ - 1, SLEN - 1);
    const int ktEnd = lastQ / BKV;

    for (int kt = 0; kt <= ktEnd; kt++) {
        const int j0 = kt * BKV;
        __syncthreads();   // protect Qs first iter / Ks,Vs reuse
        // load K,V tiles (zero-fill past S)
#pragma unroll
        for (int it = 0; it < 8; it++) {
            const int f  = tid + it * 128;   // 0..1023
            const int r  = f >> 4;
            const int c4 = f & 15;
            const int gr = j0 + r;
            float4 kv = make_float4(0.f, 0.f, 0.f, 0.f);
            float4 vv = make_float4(0.f, 0.f, 0.f, 0.f);
            if (gr < SLEN) {
                const size_t off = (baseRow + gr) * NSTATE + colOff + c4 * 4;
                kv = *(const float4*)(K + off);
                vv = *(const float4*)(V + off);
            }
            *(float4*)&Ks[r * QPAD + c4 * 4] = kv;
            *(float4*)&Vs[r * QPAD + c4 * 4] = vv;
        }
        __syncthreads();

        // scores: s[j] = q_row . k_j     (Ks reads are warp-uniform broadcasts)
        float s[BKV];
#pragma unroll
        for (int j = 0; j < BKV; j++) s[j] = 0.f;
#pragma unroll
        for (int ds = 0; ds < 16; ds++) {
            const float4 q4 = *(const float4*)&Qs[tid * QPAD + ds * 4];
#pragma unroll
            for (int j = 0; j < BKV; j++) {
                const float4 k4 = *(const float4*)&Ks[j * QPAD + ds * 4];
                s[j] = fmaf(q4.x, k4.x, s[j]);
                s[j] = fmaf(q4.y, k4.y, s[j]);
                s[j] = fmaf(q4.z, k4.z, s[j]);
                s[j] = fmaf(q4.w, k4.w, s[j]);
            }
        }

        int jlim = row - j0;                  // causal: j_global <= row
        const int jmaxS = SLEN - 1 - j0;      // key in-range
        if (jmaxS < jlim) jlim = jmaxS;
        if (jlim > BKV - 1) jlim = BKV - 1;

        if (jlim >= 0) {
            float newm = m;
#pragma unroll
            for (int j = 0; j < BKV; j++) {
                const float t = s[j] * 0.125f;    // 1/sqrt(64)
                s[j] = t;
                if (j <= jlim) newm = fmaxf(newm, t);
            }
            const float corr = __expf(m - newm);
            m = newm;
            float psum = 0.f;
#pragma unroll
            for (int j = 0; j < BKV; j++) {
                const float p = (j <= jlim) ? __expf(s[j] - newm) : 0.f;
                s[j] = p;
                psum += p;
            }
            l = l * corr + psum;
#pragma unroll
            for (int d = 0; d < HDIM; d++) acc[d] *= corr;
            // PV: acc += p_j * v_j       (Vs reads are warp-uniform broadcasts)
#pragma unroll
            for (int j = 0; j < BKV; j++) {
                const float p = s[j];
#pragma unroll
                for (int ds = 0; ds < 16; ds++) {
                    const float4 v4 = *(const float4*)&Vs[j * QPAD + ds * 4];
                    acc[ds * 4 + 0] = fmaf(p, v4.x, acc[ds * 4 + 0]);
                    acc[ds * 4 + 1] = fmaf(p, v4.y, acc[ds * 4 + 1]);
                    acc[ds * 4 + 2] = fmaf(p, v4.z, acc[ds * 4 + 2]);
                    acc[ds * 4 + 3] = fmaf(p, v4.w, acc[ds * 4 + 3]);
                }
            }
        }
    }

    if (row < SLEN) {
        const float inv = 1.f / l;
        float* op = O + (baseRow + row) * NSTATE + colOff;
#pragma unroll
        for (int ds = 0; ds < 16; ds++) {
            float4 o;
            o.x = acc[ds * 4 + 0] * inv;
            o.y = acc[ds * 4 + 1] * inv;
            o.z = acc[ds * 4 + 2] * inv;
            o.w = acc[ds * 4 + 3] * inv;
            *(float4*)(op + ds * 4) = o;
        }
    }
}

// ---------------- launch -----------------------------------------------------
extern "C" void kernel_launch(void* const* d_in, const int* in_sizes, int n_in,
                              void* d_out, int out_size)
{
    const float* x  = (const float*)d_in[0];
    // d_in[1] = mask (causal, implemented analytically)
    const float* Wq = (const float*)d_in[2];
    const float* bq = (const float*)d_in[3];
    const float* Wk = (const float*)d_in[4];
    const float* Wv = (const float*)d_in[5];
    const float* bv = (const float*)d_in[6];
    const float* Wo = (const float*)d_in[7];
    const float* bo = (const float*)d_in[8];
    float* out = (float*)d_out;

    float *pQ, *pK, *pV, *pO;
    cudaGetSymbolAddress((void**)&pQ, g_Q);
    cudaGetSymbolAddress((void**)&pK, g_K);
    cudaGetSymbolAddress((void**)&pV, g_V);
    cudaGetSymbolAddress((void**)&pO, g_O);

    const dim3 ggrid(NSTATE / BN, (MROWS + BM - 1) / BM);   // 8 x 94
    gemm_bias_kernel<<<ggrid, 256>>>(x, Wq, bq, pQ, MROWS);
    gemm_bias_kernel<<<ggrid, 256>>>(x, Wk, nullptr, pK, MROWS);
    gemm_bias_kernel<<<ggrid, 256>>>(x, Wv, bv, pV, MROWS);

    cudaFuncSetAttribute(flash_attn_kernel,
                         cudaFuncAttributeMaxDynamicSharedMemorySize, SMEM_BYTES);
    const dim3 agrid((SLEN + BQ - 1) / BQ, BATCH * NHEAD);  // 12 x 128
    flash_attn_kernel<<<agrid, 128, SMEM_BYTES>>>(pQ, pK, pV, pO);

    gemm_bias_kernel<<<ggrid, 256>>>(pO, Wo, bo, out, MROWS);
}

// round 3
// speedup vs baseline: 1.2817x; 1.2817x over previous
#include <cuda_runtime.h>
#include <cuda_bf16.h>
#include <cstdint>

#define BATCH  8
#define SLEN   1500
#define NSTATE 1024
#define NHEAD  16
#define HDIM   64
#define MROWS  (BATCH * SLEN)   // 12000

// ---------------- scratch (static device globals; no allocation) -------------
__device__ float g_Q[(size_t)MROWS * NSTATE];
__device__ float g_K[(size_t)MROWS * NSTATE];
__device__ float g_V[(size_t)MROWS * NSTATE];
__device__ float g_O[(size_t)MROWS * NSTATE];

__device__ __nv_bfloat16 g_Xhi[(size_t)MROWS * NSTATE];
__device__ __nv_bfloat16 g_Xlo[(size_t)MROWS * NSTATE];
__device__ __nv_bfloat16 g_Ohi[(size_t)MROWS * NSTATE];
__device__ __nv_bfloat16 g_Olo[(size_t)MROWS * NSTATE];
__device__ __nv_bfloat16 g_Whi[4][(size_t)NSTATE * NSTATE];
__device__ __nv_bfloat16 g_Wlo[4][(size_t)NSTATE * NSTATE];

__device__ __forceinline__ uint32_t smem_u32(const void* p) {
    uint32_t a;
    asm("{ .reg .u64 t; cvta.to.shared.u64 t, %1; cvt.u32.u64 %0, t; }"
        : "=r"(a) : "l"(p));
    return a;
}

#define LDSM_X4(r0, r1, r2, r3, addr)                                            \
    asm volatile("ldmatrix.sync.aligned.m8n8.x4.shared.b16 {%0,%1,%2,%3}, [%4];" \
                 : "=r"(r0), "=r"(r1), "=r"(r2), "=r"(r3) : "r"(addr))

#define MMA_BF16(c0, c1, c2, c3, a0, a1, a2, a3, b0, b1)                         \
    asm volatile("mma.sync.aligned.m16n8k16.row.col.f32.bf16.bf16.f32 "          \
                 "{%0,%1,%2,%3}, {%4,%5,%6,%7}, {%8,%9}, {%0,%1,%2,%3};"         \
                 : "+f"(c0), "+f"(c1), "+f"(c2), "+f"(c3)                        \
                 : "r"(a0), "r"(a1), "r"(a2), "r"(a3), "r"(b0), "r"(b1))

// ======================= split fp32 -> bf16 hi/lo ============================
__global__ __launch_bounds__(256) void split_bf16_kernel(
    const float* __restrict__ in, __nv_bfloat16* __restrict__ hi,
    __nv_bfloat16* __restrict__ lo, int n4)
{
    int i = blockIdx.x * blockDim.x + threadIdx.x;
    if (i < n4) {
        float4 v = *(const float4*)(in + (size_t)i * 4);
        __nv_bfloat16 hx = __float2bfloat16(v.x);
        __nv_bfloat16 hy = __float2bfloat16(v.y);
        __nv_bfloat16 hz = __float2bfloat16(v.z);
        __nv_bfloat16 hw = __float2bfloat16(v.w);
        __nv_bfloat162 h0 = {hx, hy}, h1 = {hz, hw};
        __nv_bfloat162 l0 = {__float2bfloat16(v.x - __bfloat162float(hx)),
                             __float2bfloat16(v.y - __bfloat162float(hy))};
        __nv_bfloat162 l1 = {__float2bfloat16(v.z - __bfloat162float(hz)),
                             __float2bfloat16(v.w - __bfloat162float(hw))};
        *(__nv_bfloat162*)(hi + (size_t)i * 4)     = h0;
        *(__nv_bfloat162*)(hi + (size_t)i * 4 + 2) = h1;
        *(__nv_bfloat162*)(lo + (size_t)i * 4)     = l0;
        *(__nv_bfloat162*)(lo + (size_t)i * 4 + 2) = l1;
    }
}

// ======== HMMA GEMM: C[M,1024] = (Ahi+Alo) @ (Bhi+Blo)^T + bias ==============
// A row-major [M,1024]; B (weights) row-major [1024 n, 1024 k] (K-major, so the
// col-major B operand of mma.row.col is loaded with PLAIN ldmatrix).
// CTA tile 128x128, BK=32; 8 warps in 2x4; warp tile 64x32.
#define GBK   32
#define GPAD  40          // 32 + 8 halves: ldmatrix rows hit all 32 banks
#define GK_ITERS (NSTATE / GBK)   // 32

__global__ __launch_bounds__(256) void hmma_gemm_kernel(
    const __nv_bfloat16* __restrict__ Ahi, const __nv_bfloat16* __restrict__ Alo,
    const __nv_bfloat16* __restrict__ Bhi, const __nv_bfloat16* __restrict__ Blo,
    const float* __restrict__ bias, float* __restrict__ C, int M)
{
    __shared__ __align__(16) __nv_bfloat16 sAh[128 * GPAD];
    __shared__ __align__(16) __nv_bfloat16 sAl[128 * GPAD];
    __shared__ __align__(16) __nv_bfloat16 sBh[128 * GPAD];
    __shared__ __align__(16) __nv_bfloat16 sBl[128 * GPAD];

    const int tid  = threadIdx.x;
    const int wid  = tid >> 5;
    const int lane = tid & 31;
    const int m0 = blockIdx.y * 128;
    const int n0 = blockIdx.x * 128;
    const int mbase = (wid >> 2) * 64;   // warp m offset
    const int nbase = (wid & 3) * 32;    // warp n offset

    const uint32_t uAh = smem_u32(sAh), uAl = smem_u32(sAl);
    const uint32_t uBh = smem_u32(sBh), uBl = smem_u32(sBl);

    float acc[4][4][4];
#pragma unroll
    for (int i = 0; i < 4; i++)
#pragma unroll
        for (int j = 0; j < 4; j++)
#pragma unroll
            for (int q = 0; q < 4; q++) acc[i][j][q] = 0.f;

    // ldmatrix source addresses (constant across k loop except k offset)
    // A frag tile (16x16): rows lane&15, k half-offset (lane>>4)*8
    const int aRow = lane & 15, aKof = (lane >> 4) * 8;
    // B frag pair (n16 x k16): group = lane>>3: n_off=(g>>1)*8+(lane&7), k_off=(g&1)*8
    const int bNof = ((lane >> 4) * 8) + (lane & 7);
    const int bKof = ((lane >> 3) & 1) * 8;

    for (int kit = 0; kit < GK_ITERS; kit++) {
        const int k0 = kit * GBK;
        // ---- load tiles: 512 16B-chunks per array, 2 per thread ----
#pragma unroll
        for (int rep = 0; rep < 2; rep++) {
            const int id  = tid + rep * 256;
            const int row = id >> 2;
            const int c   = id & 3;
            const int so  = row * GPAD + c * 8;
            const int gm  = m0 + row;
            float4 vh = make_float4(0.f, 0.f, 0.f, 0.f);
            float4 vl = make_float4(0.f, 0.f, 0.f, 0.f);
            if (gm < M) {
                const size_t go = (size_t)gm * NSTATE + k0 + c * 8;
                vh = *(const float4*)(Ahi + go);
                vl = *(const float4*)(Alo + go);
            }
            *(float4*)(sAh + so) = vh;
            *(float4*)(sAl + so) = vl;
            const size_t bo = (size_t)(n0 + row) * NSTATE + k0 + c * 8;
            *(float4*)(sBh + so) = *(const float4*)(Bhi + bo);
            *(float4*)(sBl + so) = *(const float4*)(Blo + bo);
        }
        __syncthreads();

#pragma unroll
        for (int ks = 0; ks < 2; ks++) {
            const int kof = ks * 16;
            uint32_t ah[4][4], al[4][4];
#pragma unroll
            for (int mt = 0; mt < 4; mt++) {
                const uint32_t off =
                    (uint32_t)((mbase + mt * 16 + aRow) * GPAD + kof + aKof) * 2;
                LDSM_X4(ah[mt][0], ah[mt][1], ah[mt][2], ah[mt][3], uAh + off);
                LDSM_X4(al[mt][0], al[mt][1], al[mt][2], al[mt][3], uAl + off);
            }
            uint32_t bh[4][2], bl[4][2];
#pragma unroll
            for (int np = 0; np < 2; np++) {
                const uint32_t off =
                    (uint32_t)((nbase + np * 16 + bNof) * GPAD + kof + bKof) * 2;
                LDSM_X4(bh[np * 2][0], bh[np * 2][1], bh[np * 2 + 1][0], bh[np * 2 + 1][1],
                        uBh + off);
                LDSM_X4(bl[np * 2][0], bl[np * 2][1], bl[np * 2 + 1][0], bl[np * 2 + 1][1],
                        uBl + off);
            }
#pragma unroll
            for (int mt = 0; mt < 4; mt++)
#pragma unroll
                for (int nt = 0; nt < 4; nt++) {
                    float* c4 = acc[mt][nt];
                    MMA_BF16(c4[0], c4[1], c4[2], c4[3],
                             ah[mt][0], ah[mt][1], ah[mt][2], ah[mt][3],
                             bh[nt][0], bh[nt][1]);
                    MMA_BF16(c4[0], c4[1], c4[2], c4[3],
                             ah[mt][0], ah[mt][1], ah[mt][2], ah[mt][3],
                             bl[nt][0], bl[nt][1]);
                    MMA_BF16(c4[0], c4[1], c4[2], c4[3],
                             al[mt][0], al[mt][1], al[mt][2], al[mt][3],
                             bh[nt][0], bh[nt][1]);
                }
        }
        __syncthreads();
    }

    // ---- epilogue: +bias, store fp32 ----
    const int lr = lane >> 2;            // 0..7
    const int lc = (lane & 3) * 2;       // 0,2,4,6
#pragma unroll
    for (int mt = 0; mt < 4; mt++) {
#pragma unroll
        for (int half = 0; half < 2; half++) {
            const int gm = m0 + mbase + mt * 16 + half * 8 + lr;
            if (gm < M) {
                float* cp = C + (size_t)gm * NSTATE;
#pragma unroll
                for (int nt = 0; nt < 4; nt++) {
                    const int gn = n0 + nbase + nt * 8 + lc;
                    float2 o;
                    o.x = acc[mt][nt][half * 2 + 0];
                    o.y = acc[mt][nt][half * 2 + 1];
                    if (bias) {
                        o.x += bias[gn];
                        o.y += bias[gn + 1];
                    }
                    *(float2*)(cp + gn) = o;
                }
            }
        }
    }
}

// ---------------- Flash attention (causal, fp32) — unchanged -----------------
#define BQ    128
#define BKV   64
#define QPAD  68
#define SMEM_BYTES ((BQ + 2 * BKV) * QPAD * 4)

__global__ __launch_bounds__(128) void flash_attn_kernel(
    const float* __restrict__ Q, const float* __restrict__ K,
    const float* __restrict__ V, float* __restrict__ O)
{
    extern __shared__ __align__(16) float fsmem[];
    float* Qs = fsmem;
    float* Ks = fsmem + BQ * QPAD;
    float* Vs = Ks + BKV * QPAD;

    const int tid = threadIdx.x;
    const int bh  = blockIdx.y;
    const int b   = bh >> 4;
    const int h   = bh & 15;
    const int q0  = blockIdx.x * BQ;
    const int row = q0 + tid;
    const size_t baseRow = (size_t)b * SLEN;
    const int colOff = h * HDIM;

#pragma unroll
    for (int it = 0; it < 16; it++) {
        const int f  = tid + it * 128;
        const int r  = f >> 4;
        const int c4 = f & 15;
        const int gr = q0 + r;
        float4 v = make_float4(0.f, 0.f, 0.f, 0.f);
        if (gr < SLEN)
            v = *(const float4*)(Q + (baseRow + gr) * NSTATE + colOff + c4 * 4);
        *(float4*)&Qs[r * QPAD + c4 * 4] = v;
    }

    float m = -1e30f, l = 0.f;
    float acc[HDIM];
#pragma unroll
    for (int d = 0; d < HDIM; d++) acc[d] = 0.f;

    const int lastQ = min(q0 + BQ - 1, SLEN - 1);
    const int ktEnd = lastQ / BKV;

    for (int kt = 0; kt <= ktEnd; kt++) {
        const int j0 = kt * BKV;
        __syncthreads();
#pragma unroll
        for (int it = 0; it < 8; it++) {
            const int f  = tid + it * 128;
            const int r  = f >> 4;
            const int c4 = f & 15;
            const int gr = j0 + r;
            float4 kv = make_float4(0.f, 0.f, 0.f, 0.f);
            float4 vv = make_float4(0.f, 0.f, 0.f, 0.f);
            if (gr < SLEN) {
                const size_t off = (baseRow + gr) * NSTATE + colOff + c4 * 4;
                kv = *(const float4*)(K + off);
                vv = *(const float4*)(V + off);
            }
            *(float4*)&Ks[r * QPAD + c4 * 4] = kv;
            *(float4*)&Vs[r * QPAD + c4 * 4] = vv;
        }
        __syncthreads();

        float s[BKV];
#pragma unroll
        for (int j = 0; j < BKV; j++) s[j] = 0.f;
#pragma unroll
        for (int ds = 0; ds < 16; ds++) {
            const float4 q4 = *(const float4*)&Qs[tid * QPAD + ds * 4];
#pragma unroll
            for (int j = 0; j < BKV; j++) {
                const float4 k4 = *(const float4*)&Ks[j * QPAD + ds * 4];
                s[j] = fmaf(q4.x, k4.x, s[j]);
                s[j] = fmaf(q4.y, k4.y, s[j]);
                s[j] = fmaf(q4.z, k4.z, s[j]);
                s[j] = fmaf(q4.w, k4.w, s[j]);
            }
        }

        int jlim = row - j0;
        const int jmaxS = SLEN - 1 - j0;
        if (jmaxS < jlim) jlim = jmaxS;
        if (jlim > BKV - 1) jlim = BKV - 1;

        if (jlim >= 0) {
            float newm = m;
#pragma unroll
            for (int j = 0; j < BKV; j++) {
                const float t = s[j] * 0.125f;
                s[j] = t;
                if (j <= jlim) newm = fmaxf(newm, t);
            }
            const float corr = __expf(m - newm);
            m = newm;
            float psum = 0.f;
#pragma unroll
            for (int j = 0; j < BKV; j++) {
                const float p = (j <= jlim) ? __expf(s[j] - newm) : 0.f;
                s[j] = p;
                psum += p;
            }
            l = l * corr + psum;
#pragma unroll
            for (int d = 0; d < HDIM; d++) acc[d] *= corr;
#pragma unroll
            for (int j = 0; j < BKV; j++) {
                const float p = s[j];
#pragma unroll
                for (int ds = 0; ds < 16; ds++) {
                    const float4 v4 = *(const float4*)&Vs[j * QPAD + ds * 4];
                    acc[ds * 4 + 0] = fmaf(p, v4.x, acc[ds * 4 + 0]);
                    acc[ds * 4 + 1] = fmaf(p, v4.y, acc[ds * 4 + 1]);
                    acc[ds * 4 + 2] = fmaf(p, v4.z, acc[ds * 4 + 2]);
                    acc[ds * 4 + 3] = fmaf(p, v4.w, acc[ds * 4 + 3]);
                }
            }
        }
    }

    if (row < SLEN) {
        const float inv = 1.f / l;
        float* op = O + (baseRow + row) * NSTATE + colOff;
#pragma unroll
        for (int ds = 0; ds < 16; ds++) {
            float4 o;
            o.x = acc[ds * 4 + 0] * inv;
            o.y = acc[ds * 4 + 1] * inv;
            o.z = acc[ds * 4 + 2] * inv;
            o.w = acc[ds * 4 + 3] * inv;
            *(float4*)(op + ds * 4) = o;
        }
    }
}

// ---------------- launch -----------------------------------------------------
extern "C" void kernel_launch(void* const* d_in, const int* in_sizes, int n_in,
                              void* d_out, int out_size)
{
    const float* x  = (const float*)d_in[0];
    const float* Wq = (const float*)d_in[2];
    const float* bq = (const float*)d_in[3];
    const float* Wk = (const float*)d_in[4];
    const float* Wv = (const float*)d_in[5];
    const float* bv = (const float*)d_in[6];
    const float* Wo = (const float*)d_in[7];
    const float* bo = (const float*)d_in[8];
    float* out = (float*)d_out;

    float *pQ, *pK, *pV, *pO;
    cudaGetSymbolAddress((void**)&pQ, g_Q);
    cudaGetSymbolAddress((void**)&pK, g_K);
    cudaGetSymbolAddress((void**)&pV, g_V);
    cudaGetSymbolAddress((void**)&pO, g_O);
    __nv_bfloat16 *xhi, *xlo, *ohi, *olo, *whi, *wlo;
    cudaGetSymbolAddress((void**)&xhi, g_Xhi);
    cudaGetSymbolAddress((void**)&xlo, g_Xlo);
    cudaGetSymbolAddress((void**)&ohi, g_Ohi);
    cudaGetSymbolAddress((void**)&olo, g_Olo);
    cudaGetSymbolAddress((void**)&whi, g_Whi);
    cudaGetSymbolAddress((void**)&wlo, g_Wlo);
    const size_t WSZ = (size_t)NSTATE * NSTATE;

    cudaFuncSetAttribute(flash_attn_kernel,
                         cudaFuncAttributeMaxDynamicSharedMemorySize, SMEM_BYTES);

    const int xn4 = MROWS * NSTATE / 4;
    const int wn4 = NSTATE * NSTATE / 4;
    split_bf16_kernel<<<(xn4 + 255) / 256, 256>>>(x, xhi, xlo, xn4);
    split_bf16_kernel<<<(wn4 + 255) / 256, 256>>>(Wq, whi + 0 * WSZ, wlo + 0 * WSZ, wn4);
    split_bf16_kernel<<<(wn4 + 255) / 256, 256>>>(Wk, whi + 1 * WSZ, wlo + 1 * WSZ, wn4);
    split_bf16_kernel<<<(wn4 + 255) / 256, 256>>>(Wv, whi + 2 * WSZ, wlo + 2 * WSZ, wn4);
    split_bf16_kernel<<<(wn4 + 255) / 256, 256>>>(Wo, whi + 3 * WSZ, wlo + 3 * WSZ, wn4);

    const dim3 ggrid(NSTATE / 128, (MROWS + 127) / 128);   // 8 x 94
    hmma_gemm_kernel<<<ggrid, 256>>>(xhi, xlo, whi + 0 * WSZ, wlo + 0 * WSZ, bq, pQ, MROWS);
    hmma_gemm_kernel<<<ggrid, 256>>>(xhi, xlo, whi + 1 * WSZ, wlo + 1 * WSZ, nullptr, pK, MROWS);
    hmma_gemm_kernel<<<ggrid, 256>>>(xhi, xlo, whi + 2 * WSZ, wlo + 2 * WSZ, bv, pV, MROWS);

    const dim3 agrid((SLEN + BQ - 1) / BQ, BATCH * NHEAD);  // 12 x 128
    flash_attn_kernel<<<agrid, 128, SMEM_BYTES>>>(pQ, pK, pV, pO);

    split_bf16_kernel<<<(xn4 + 255) / 256, 256>>>(pO, ohi, olo, xn4);
    hmma_gemm_kernel<<<ggrid, 256>>>(ohi, olo, whi + 3 * WSZ, wlo + 3 * WSZ, bo, out, MROWS);
}

// round 4
// speedup vs baseline: 3.5204x; 2.7467x over previous
#include <cuda_runtime.h>
#include <cuda_bf16.h>
#include <cuda_fp16.h>
#include <cstdint>

#define BATCH  8
#define SLEN   1500
#define NSTATE 1024
#define NHEAD  16
#define HDIM   64
#define MROWS  (BATCH * SLEN)   // 12000

// ---------------- scratch (static device globals; no allocation) -------------
__device__ __nv_bfloat16 g_Xhi[(size_t)MROWS * NSTATE];
__device__ __nv_bfloat16 g_Xlo[(size_t)MROWS * NSTATE];
__device__ __nv_bfloat16 g_Qhi[(size_t)MROWS * NSTATE];
__device__ __nv_bfloat16 g_Qlo[(size_t)MROWS * NSTATE];
__device__ __nv_bfloat16 g_Khi[(size_t)MROWS * NSTATE];
__device__ __nv_bfloat16 g_Klo[(size_t)MROWS * NSTATE];
__device__ __half        g_Vh [(size_t)MROWS * NSTATE];
__device__ __nv_bfloat16 g_Ohi[(size_t)MROWS * NSTATE];
__device__ __nv_bfloat16 g_Olo[(size_t)MROWS * NSTATE];
__device__ __nv_bfloat16 g_Whi[4][(size_t)NSTATE * NSTATE];
__device__ __nv_bfloat16 g_Wlo[4][(size_t)NSTATE * NSTATE];

__device__ __forceinline__ uint32_t smem_u32(const void* p) {
    uint32_t a;
    asm("{ .reg .u64 t; cvta.to.shared.u64 t, %1; cvt.u32.u64 %0, t; }"
        : "=r"(a) : "l"(p));
    return a;
}

#define LDSM_X4(r0, r1, r2, r3, addr)                                            \
    asm volatile("ldmatrix.sync.aligned.m8n8.x4.shared.b16 {%0,%1,%2,%3}, [%4];" \
                 : "=r"(r0), "=r"(r1), "=r"(r2), "=r"(r3) : "r"(addr))

#define LDSM_X4_T(r0, r1, r2, r3, addr)                                          \
    asm volatile("ldmatrix.sync.aligned.m8n8.x4.trans.shared.b16 {%0,%1,%2,%3}, [%4];" \
                 : "=r"(r0), "=r"(r1), "=r"(r2), "=r"(r3) : "r"(addr))

#define MMA_BF16(c0, c1, c2, c3, a0, a1, a2, a3, b0, b1)                         \
    asm volatile("mma.sync.aligned.m16n8k16.row.col.f32.bf16.bf16.f32 "          \
                 "{%0,%1,%2,%3}, {%4,%5,%6,%7}, {%8,%9}, {%0,%1,%2,%3};"         \
                 : "+f"(c0), "+f"(c1), "+f"(c2), "+f"(c3)                        \
                 : "r"(a0), "r"(a1), "r"(a2), "r"(a3), "r"(b0), "r"(b1))

#define MMA_F16(c0, c1, c2, c3, a0, a1, a2, a3, b0, b1)                          \
    asm volatile("mma.sync.aligned.m16n8k16.row.col.f32.f16.f16.f32 "            \
                 "{%0,%1,%2,%3}, {%4,%5,%6,%7}, {%8,%9}, {%0,%1,%2,%3};"         \
                 : "+f"(c0), "+f"(c1), "+f"(c2), "+f"(c3)                        \
                 : "r"(a0), "r"(a1), "r"(a2), "r"(a3), "r"(b0), "r"(b1))

// pack two fp32 to half2: lo half = first arg
#define PACK_H2(d, vlo, vhi)                                                     \
    asm("cvt.rn.f16x2.f32 %0, %1, %2;" : "=r"(d) : "f"(vhi), "f"(vlo))

// ======================= split fp32 -> bf16 hi/lo ============================
__global__ __launch_bounds__(256) void split_bf16_kernel(
    const float* __restrict__ in, __nv_bfloat16* __restrict__ hi,
    __nv_bfloat16* __restrict__ lo, int n4)
{
    int i = blockIdx.x * blockDim.x + threadIdx.x;
    if (i < n4) {
        float4 v = *(const float4*)(in + (size_t)i * 4);
        __nv_bfloat16 hx = __float2bfloat16(v.x);
        __nv_bfloat16 hy = __float2bfloat16(v.y);
        __nv_bfloat16 hz = __float2bfloat16(v.z);
        __nv_bfloat16 hw = __float2bfloat16(v.w);
        __nv_bfloat162 h0 = {hx, hy}, h1 = {hz, hw};
        __nv_bfloat162 l0 = {__float2bfloat16(v.x - __bfloat162float(hx)),
                             __float2bfloat16(v.y - __bfloat162float(hy))};
        __nv_bfloat162 l1 = {__float2bfloat16(v.z - __bfloat162float(hz)),
                             __float2bfloat16(v.w - __bfloat162float(hw))};
        *(__nv_bfloat162*)(hi + (size_t)i * 4)     = h0;
        *(__nv_bfloat162*)(hi + (size_t)i * 4 + 2) = h1;
        *(__nv_bfloat162*)(lo + (size_t)i * 4)     = l0;
        *(__nv_bfloat162*)(lo + (size_t)i * 4 + 2) = l1;
    }
}

// ======== HMMA GEMM: C = (Ahi+Alo) @ (Bhi+Blo)^T + bias, templated out ======
#define GBK   32
#define GPAD  40
#define GK_ITERS (NSTATE / GBK)   // 32

#define OUT_F32  0
#define OUT_HILO 1
#define OUT_F16  2

template <int MODE>
__global__ __launch_bounds__(256) void hmma_gemm_kernel(
    const __nv_bfloat16* __restrict__ Ahi, const __nv_bfloat16* __restrict__ Alo,
    const __nv_bfloat16* __restrict__ Bhi, const __nv_bfloat16* __restrict__ Blo,
    const float* __restrict__ bias, float* __restrict__ Cf,
    __nv_bfloat16* __restrict__ Chi, __nv_bfloat16* __restrict__ Clo,
    __half* __restrict__ Ch, int M)
{
    __shared__ __align__(16) __nv_bfloat16 sAh[128 * GPAD];
    __shared__ __align__(16) __nv_bfloat16 sAl[128 * GPAD];
    __shared__ __align__(16) __nv_bfloat16 sBh[128 * GPAD];
    __shared__ __align__(16) __nv_bfloat16 sBl[128 * GPAD];

    const int tid  = threadIdx.x;
    const int wid  = tid >> 5;
    const int lane = tid & 31;
    const int m0 = blockIdx.y * 128;
    const int n0 = blockIdx.x * 128;
    const int mbase = (wid >> 2) * 64;
    const int nbase = (wid & 3) * 32;

    const uint32_t uAh = smem_u32(sAh), uAl = smem_u32(sAl);
    const uint32_t uBh = smem_u32(sBh), uBl = smem_u32(sBl);

    float acc[4][4][4];
#pragma unroll
    for (int i = 0; i < 4; i++)
#pragma unroll
        for (int j = 0; j < 4; j++)
#pragma unroll
            for (int q = 0; q < 4; q++) acc[i][j][q] = 0.f;

    const int aRow = lane & 15, aKof = (lane >> 4) * 8;
    const int bNof = ((lane >> 4) * 8) + (lane & 7);
    const int bKof = ((lane >> 3) & 1) * 8;

    for (int kit = 0; kit < GK_ITERS; kit++) {
        const int k0 = kit * GBK;
#pragma unroll
        for (int rep = 0; rep < 2; rep++) {
            const int id  = tid + rep * 256;
            const int row = id >> 2;
            const int c   = id & 3;
            const int so  = row * GPAD + c * 8;
            const int gm  = m0 + row;
            float4 vh = make_float4(0.f, 0.f, 0.f, 0.f);
            float4 vl = make_float4(0.f, 0.f, 0.f, 0.f);
            if (gm < M) {
                const size_t go = (size_t)gm * NSTATE + k0 + c * 8;
                vh = *(const float4*)(Ahi + go);
                vl = *(const float4*)(Alo + go);
            }
            *(float4*)(sAh + so) = vh;
            *(float4*)(sAl + so) = vl;
            const size_t bo = (size_t)(n0 + row) * NSTATE + k0 + c * 8;
            *(float4*)(sBh + so) = *(const float4*)(Bhi + bo);
            *(float4*)(sBl + so) = *(const float4*)(Blo + bo);
        }
        __syncthreads();

#pragma unroll
        for (int ks = 0; ks < 2; ks++) {
            const int kof = ks * 16;
            uint32_t ah[4][4], al[4][4];
#pragma unroll
            for (int mt = 0; mt < 4; mt++) {
                const uint32_t off =
                    (uint32_t)((mbase + mt * 16 + aRow) * GPAD + kof + aKof) * 2;
                LDSM_X4(ah[mt][0], ah[mt][1], ah[mt][2], ah[mt][3], uAh + off);
                LDSM_X4(al[mt][0], al[mt][1], al[mt][2], al[mt][3], uAl + off);
            }
            uint32_t bh[4][2], bl[4][2];
#pragma unroll
            for (int np = 0; np < 2; np++) {
                const uint32_t off =
                    (uint32_t)((nbase + np * 16 + bNof) * GPAD + kof + bKof) * 2;
                LDSM_X4(bh[np * 2][0], bh[np * 2][1], bh[np * 2 + 1][0], bh[np * 2 + 1][1],
                        uBh + off);
                LDSM_X4(bl[np * 2][0], bl[np * 2][1], bl[np * 2 + 1][0], bl[np * 2 + 1][1],
                        uBl + off);
            }
#pragma unroll
            for (int mt = 0; mt < 4; mt++)
#pragma unroll
                for (int nt = 0; nt < 4; nt++) {
                    float* c4 = acc[mt][nt];
                    MMA_BF16(c4[0], c4[1], c4[2], c4[3],
                             ah[mt][0], ah[mt][1], ah[mt][2], ah[mt][3],
                             bh[nt][0], bh[nt][1]);
                    MMA_BF16(c4[0], c4[1], c4[2], c4[3],
                             ah[mt][0], ah[mt][1], ah[mt][2], ah[mt][3],
                             bl[nt][0], bl[nt][1]);
                    MMA_BF16(c4[0], c4[1], c4[2], c4[3],
                             al[mt][0], al[mt][1], al[mt][2], al[mt][3],
                             bh[nt][0], bh[nt][1]);
                }
        }
        __syncthreads();
    }

    const int lr = lane >> 2;
    const int lc = (lane & 3) * 2;
#pragma unroll
    for (int mt = 0; mt < 4; mt++) {
#pragma unroll
        for (int half_ = 0; half_ < 2; half_++) {
            const int gm = m0 + mbase + mt * 16 + half_ * 8 + lr;
            if (gm < M) {
#pragma unroll
                for (int nt = 0; nt < 4; nt++) {
                    const int gn = n0 + nbase + nt * 8 + lc;
                    float vx = acc[mt][nt][half_ * 2 + 0];
                    float vy = acc[mt][nt][half_ * 2 + 1];
                    if (bias) { vx += bias[gn]; vy += bias[gn + 1]; }
                    const size_t idx = (size_t)gm * NSTATE + gn;
                    if (MODE == OUT_F32) {
                        *(float2*)(Cf + idx) = make_float2(vx, vy);
                    } else if (MODE == OUT_HILO) {
                        __nv_bfloat16 hx = __float2bfloat16(vx);
                        __nv_bfloat16 hy = __float2bfloat16(vy);
                        __nv_bfloat162 h = {hx, hy};
                        __nv_bfloat162 l = {__float2bfloat16(vx - __bfloat162float(hx)),
                                            __float2bfloat16(vy - __bfloat162float(hy))};
                        *(__nv_bfloat162*)(Chi + idx) = h;
                        *(__nv_bfloat162*)(Clo + idx) = l;
                    } else {
                        __half2 hv = {__float2half_rn(vx), __float2half_rn(vy)};
                        *(__half2*)(Ch + idx) = hv;
                    }
                }
            }
        }
    }
}

// ================= HMMA flash attention (causal) =============================
// Q,K split-bf16 (3 MMAs), P/V fp16 (1 MMA). BQ=128, BKV=64, 8 warps.
#define AQ    128
#define AKV   64
#define APAD  72    // halves per row: 144B, conflict-free & 16B aligned

__global__ __launch_bounds__(256) void flash_hmma_kernel(
    const __nv_bfloat16* __restrict__ Qhi, const __nv_bfloat16* __restrict__ Qlo,
    const __nv_bfloat16* __restrict__ Khi, const __nv_bfloat16* __restrict__ Klo,
    const __half* __restrict__ Vh,
    __nv_bfloat16* __restrict__ Ohi, __nv_bfloat16* __restrict__ Olo)
{
    __shared__ __align__(16) __nv_bfloat16 sH[AQ * APAD];
    __shared__ __align__(16) __nv_bfloat16 sL[AQ * APAD];
    __shared__ __align__(16) __half        sV[AKV * APAD];

    const int tid  = threadIdx.x;
    const int wid  = tid >> 5;
    const int lane = tid & 31;
    const int bh = blockIdx.y;
    const int b  = bh >> 4;
    const int h  = bh & 15;
    const int q0 = blockIdx.x * AQ;
    const size_t rowBase = (size_t)b * SLEN;
    const int colOff = h * HDIM;

    const uint32_t uH = smem_u32(sH), uL = smem_u32(sL), uV = smem_u32(sV);

    // ---- stage Q tile (128 rows x 64) hi/lo into sH/sL ----
#pragma unroll
    for (int it = 0; it < 4; it++) {
        const int id = tid + it * 256;    // 0..1023
        const int r  = id >> 3;
        const int c  = id & 7;
        const int gq = q0 + r;
        uint4 vh = make_uint4(0, 0, 0, 0), vl = make_uint4(0, 0, 0, 0);
        if (gq < SLEN) {
            const size_t off = (rowBase + gq) * NSTATE + colOff + c * 8;
            vh = *(const uint4*)(Qhi + off);
            vl = *(const uint4*)(Qlo + off);
        }
        *(uint4*)(sH + r * APAD + c * 8) = vh;
        *(uint4*)(sL + r * APAD + c * 8) = vl;
    }
    __syncthreads();

    // ---- Q fragments to registers ----
    const int aRow = lane & 15, aKof = (lane >> 4) * 8;
    const int wq0 = wid * 16;
    uint32_t qh[4][4], ql[4][4];
#pragma unroll
    for (int ks = 0; ks < 4; ks++) {
        const uint32_t off = (uint32_t)((wq0 + aRow) * APAD + ks * 16 + aKof) * 2;
        LDSM_X4(qh[ks][0], qh[ks][1], qh[ks][2], qh[ks][3], uH + off);
        LDSM_X4(ql[ks][0], ql[ks][1], ql[ks][2], ql[ks][3], uL + off);
    }
    __syncthreads();

    const int gqa = q0 + wq0 + (lane >> 2);    // row for c0/c1; +8 for c2/c3
    float mr0 = -1e30f, mr1 = -1e30f, l0 = 0.f, l1 = 0.f;
    float oacc[8][4];
#pragma unroll
    for (int i = 0; i < 8; i++)
#pragma unroll
        for (int q = 0; q < 4; q++) oacc[i][q] = 0.f;

    const int bNof = ((lane >> 4) * 8) + (lane & 7);
    const int bKof = ((lane >> 3) & 1) * 8;
    const int vRow = ((lane >> 3) & 1) * 8 + (lane & 7);
    const int vCof = (lane >> 4) * 8;

    const int tEnd = min(q0 + AQ - 1, SLEN - 1) / AKV;
    for (int t = 0; t <= tEnd; t++) {
        const int j0 = t * AKV;
        // ---- load K hi/lo + V tiles ----
#pragma unroll
        for (int it = 0; it < 2; it++) {
            const int id = tid + it * 256;    // 0..511
            const int r  = id >> 3;
            const int c  = id & 7;
            const int gk = j0 + r;
            uint4 vh = make_uint4(0, 0, 0, 0), vl = make_uint4(0, 0, 0, 0),
                  vv = make_uint4(0, 0, 0, 0);
            if (gk < SLEN) {
                const size_t off = (rowBase + gk) * NSTATE + colOff + c * 8;
                vh = *(const uint4*)(Khi + off);
                vl = *(const uint4*)(Klo + off);
                vv = *(const uint4*)(Vh + off);
            }
            *(uint4*)(sH + r * APAD + c * 8) = vh;
            *(uint4*)(sL + r * APAD + c * 8) = vl;
            *(uint4*)(sV + r * APAD + c * 8) = vv;
        }
        __syncthreads();

        if (j0 <= q0 + wq0 + 15) {    // warp has unmasked rows in this tile
            // ---- S = Q K^T (split-bf16, 3 MMAs) ----
            float S[8][4];
#pragma unroll
            for (int nt = 0; nt < 8; nt++)
#pragma unroll
                for (int q = 0; q < 4; q++) S[nt][q] = 0.f;
#pragma unroll
            for (int ks = 0; ks < 4; ks++) {
                uint32_t kh[8][2], kl[8][2];
#pragma unroll
                for (int np = 0; np < 4; np++) {
                    const uint32_t off =
                        (uint32_t)((np * 16 + bNof) * APAD + ks * 16 + bKof) * 2;
                    LDSM_X4(kh[np * 2][0], kh[np * 2][1],
                            kh[np * 2 + 1][0], kh[np * 2 + 1][1], uH + off);
                    LDSM_X4(kl[np * 2][0], kl[np * 2][1],
                            kl[np * 2 + 1][0], kl[np * 2 + 1][1], uL + off);
                }
#pragma unroll
                for (int nt = 0; nt < 8; nt++) {
                    MMA_BF16(S[nt][0], S[nt][1], S[nt][2], S[nt][3],
                             qh[ks][0], qh[ks][1], qh[ks][2], qh[ks][3],
                             kh[nt][0], kh[nt][1]);
                    MMA_BF16(S[nt][0], S[nt][1], S[nt][2], S[nt][3],
                             qh[ks][0], qh[ks][1], qh[ks][2], qh[ks][3],
                             kl[nt][0], kl[nt][1]);
                    MMA_BF16(S[nt][0], S[nt][1], S[nt][2], S[nt][3],
                             ql[ks][0], ql[ks][1], ql[ks][2], ql[ks][3],
                             kh[nt][0], kh[nt][1]);
                }
            }
            // ---- masked online softmax ----
            float mx0 = mr0, mx1 = mr1;
            const int jc = j0 + 2 * (lane & 3);
#pragma unroll
            for (int nt = 0; nt < 8; nt++) {
#pragma unroll
                for (int q = 0; q < 4; q++) {
                    const int jg  = jc + nt * 8 + (q & 1);
                    const int row = (q < 2) ? gqa : gqa + 8;
                    const bool ok = (jg <= row) && (jg < SLEN);
                    const float sv = ok ? S[nt][q] * 0.125f : -1e30f;
                    S[nt][q] = sv;
                    if (q < 2) mx0 = fmaxf(mx0, sv); else mx1 = fmaxf(mx1, sv);
                }
            }
            mx0 = fmaxf(mx0, __shfl_xor_sync(0xffffffffu, mx0, 1));
            mx0 = fmaxf(mx0, __shfl_xor_sync(0xffffffffu, mx0, 2));
            mx1 = fmaxf(mx1, __shfl_xor_sync(0xffffffffu, mx1, 1));
            mx1 = fmaxf(mx1, __shfl_xor_sync(0xffffffffu, mx1, 2));
            const float corr0 = __expf(mr0 - mx0);
            const float corr1 = __expf(mr1 - mx1);
            mr0 = mx0; mr1 = mx1;
            float ps0 = 0.f, ps1 = 0.f;
#pragma unroll
            for (int nt = 0; nt < 8; nt++) {
#pragma unroll
                for (int q = 0; q < 4; q++) {
                    const float p = __expf(S[nt][q] - ((q < 2) ? mx0 : mx1));
                    S[nt][q] = p;
                    if (q < 2) ps0 += p; else ps1 += p;
                }
            }
            ps0 += __shfl_xor_sync(0xffffffffu, ps0, 1);
            ps0 += __shfl_xor_sync(0xffffffffu, ps0, 2);
            ps1 += __shfl_xor_sync(0xffffffffu, ps1, 1);
            ps1 += __shfl_xor_sync(0xffffffffu, ps1, 2);
            l0 = l0 * corr0 + ps0;
            l1 = l1 * corr1 + ps1;
#pragma unroll
            for (int nt = 0; nt < 8; nt++) {
                oacc[nt][0] *= corr0; oacc[nt][1] *= corr0;
                oacc[nt][2] *= corr1; oacc[nt][3] *= corr1;
            }
            // ---- O += P V (fp16) ----
#pragma unroll
            for (int ks2 = 0; ks2 < 4; ks2++) {
                uint32_t a0, a1, a2, a3;
                PACK_H2(a0, S[2 * ks2][0],     S[2 * ks2][1]);
                PACK_H2(a1, S[2 * ks2][2],     S[2 * ks2][3]);
                PACK_H2(a2, S[2 * ks2 + 1][0], S[2 * ks2 + 1][1]);
                PACK_H2(a3, S[2 * ks2 + 1][2], S[2 * ks2 + 1][3]);
#pragma unroll
                for (int dp = 0; dp < 4; dp++) {
                    uint32_t v0, v1, v2, v3;
                    const uint32_t off =
                        (uint32_t)((ks2 * 16 + vRow) * APAD + dp * 16 + vCof) * 2;
                    LDSM_X4_T(v0, v1, v2, v3, uV + off);
                    MMA_F16(oacc[2 * dp][0], oacc[2 * dp][1],
                            oacc[2 * dp][2], oacc[2 * dp][3],
                            a0, a1, a2, a3, v0, v1);
                    MMA_F16(oacc[2 * dp + 1][0], oacc[2 * dp + 1][1],
                            oacc[2 * dp + 1][2], oacc[2 * dp + 1][3],
                            a0, a1, a2, a3, v2, v3);
                }
            }
        }
        __syncthreads();
    }

    // ---- epilogue: normalize + write bf16 hi/lo ----
    const float inv0 = (l0 > 0.f) ? 1.f / l0 : 0.f;
    const float inv1 = (l1 > 0.f) ? 1.f / l1 : 0.f;
#pragma unroll
    for (int nt = 0; nt < 8; nt++) {
        const int d = colOff + nt * 8 + 2 * (lane & 3);
        if (gqa < SLEN) {
            const float vx = oacc[nt][0] * inv0;
            const float vy = oacc[nt][1] * inv0;
            __nv_bfloat16 hx = __float2bfloat16(vx), hy = __float2bfloat16(vy);
            __nv_bfloat162 hh = {hx, hy};
            __nv_bfloat162 ll = {__float2bfloat16(vx - __bfloat162float(hx)),
                                 __float2bfloat16(vy - __bfloat162float(hy))};
            const size_t idx = (rowBase + gqa) * NSTATE + d;
            *(__nv_bfloat162*)(Ohi + idx) = hh;
            *(__nv_bfloat162*)(Olo + idx) = ll;
        }
        if (gqa + 8 < SLEN) {
            const float vx = oacc[nt][2] * inv1;
            const float vy = oacc[nt][3] * inv1;
            __nv_bfloat16 hx = __float2bfloat16(vx), hy = __float2bfloat16(vy);
            __nv_bfloat162 hh = {hx, hy};
            __nv_bfloat162 ll = {__float2bfloat16(vx - __bfloat162float(hx)),
                                 __float2bfloat16(vy - __bfloat162float(hy))};
            const size_t idx = (rowBase + gqa + 8) * NSTATE + d;
            *(__nv_bfloat162*)(Ohi + idx) = hh;
            *(__nv_bfloat162*)(Olo + idx) = ll;
        }
    }
}

// ---------------- launch -----------------------------------------------------
extern "C" void kernel_launch(void* const* d_in, const int* in_sizes, int n_in,
                              void* d_out, int out_size)
{
    const float* x  = (const float*)d_in[0];
    const float* Wq = (const float*)d_in[2];
    const float* bq = (const float*)d_in[3];
    const float* Wk = (const float*)d_in[4];
    const float* Wv = (const float*)d_in[5];
    const float* bv = (const float*)d_in[6];
    const float* Wo = (const float*)d_in[7];
    const float* bo = (const float*)d_in[8];
    float* out = (float*)d_out;

    __nv_bfloat16 *xhi, *xlo, *qhi, *qlo, *khi, *klo, *ohi, *olo, *whi, *wlo;
    __half* vh;
    cudaGetSymbolAddress((void**)&xhi, g_Xhi);
    cudaGetSymbolAddress((void**)&xlo, g_Xlo);
    cudaGetSymbolAddress((void**)&qhi, g_Qhi);
    cudaGetSymbolAddress((void**)&qlo, g_Qlo);
    cudaGetSymbolAddress((void**)&khi, g_Khi);
    cudaGetSymbolAddress((void**)&klo, g_Klo);
    cudaGetSymbolAddress((void**)&vh,  g_Vh);
    cudaGetSymbolAddress((void**)&ohi, g_Ohi);
    cudaGetSymbolAddress((void**)&olo, g_Olo);
    cudaGetSymbolAddress((void**)&whi, g_Whi);
    cudaGetSymbolAddress((void**)&wlo, g_Wlo);
    const size_t WSZ = (size_t)NSTATE * NSTATE;

    const int xn4 = MROWS * NSTATE / 4;
    const int wn4 = NSTATE * NSTATE / 4;
    split_bf16_kernel<<<(xn4 + 255) / 256, 256>>>(x, xhi, xlo, xn4);
    split_bf16_kernel<<<(wn4 + 255) / 256, 256>>>(Wq, whi + 0 * WSZ, wlo + 0 * WSZ, wn4);
    split_bf16_kernel<<<(wn4 + 255) / 256, 256>>>(Wk, whi + 1 * WSZ, wlo + 1 * WSZ, wn4);
    split_bf16_kernel<<<(wn4 + 255) / 256, 256>>>(Wv, whi + 2 * WSZ, wlo + 2 * WSZ, wn4);
    split_bf16_kernel<<<(wn4 + 255) / 256, 256>>>(Wo, whi + 3 * WSZ, wlo + 3 * WSZ, wn4);

    const dim3 ggrid(NSTATE / 128, (MROWS + 127) / 128);   // 8 x 94
    hmma_gemm_kernel<OUT_HILO><<<ggrid, 256>>>(xhi, xlo, whi + 0 * WSZ, wlo + 0 * WSZ,
                                               bq, nullptr, qhi, qlo, nullptr, MROWS);
    hmma_gemm_kernel<OUT_HILO><<<ggrid, 256>>>(xhi, xlo, whi + 1 * WSZ, wlo + 1 * WSZ,
                                               nullptr, nullptr, khi, klo, nullptr, MROWS);
    hmma_gemm_kernel<OUT_F16><<<ggrid, 256>>>(xhi, xlo, whi + 2 * WSZ, wlo + 2 * WSZ,
                                              bv, nullptr, nullptr, nullptr, vh, MROWS);

    const dim3 agrid((SLEN + AQ - 1) / AQ, BATCH * NHEAD);  // 12 x 128
    flash_hmma_kernel<<<agrid, 256>>>(qhi, qlo, khi, klo, vh, ohi, olo);

    hmma_gemm_kernel<OUT_F32><<<ggrid, 256>>>(ohi, olo, whi + 3 * WSZ, wlo + 3 * WSZ,
                                              bo, out, nullptr, nullptr, nullptr, MROWS);
}

// round 5
// speedup vs baseline: 4.0088x; 1.1387x over previous
#include <cuda_runtime.h>
#include <cuda_bf16.h>
#include <cuda_fp16.h>
#include <cstdint>

#define BATCH  8
#define SLEN   1500
#define NSTATE 1024
#define NHEAD  16
#define HDIM   64
#define MROWS  (BATCH * SLEN)   // 12000

// ---------------- scratch (static device globals; no allocation) -------------
__device__ __nv_bfloat16 g_Xhi[(size_t)MROWS * NSTATE];
__device__ __nv_bfloat16 g_Xlo[(size_t)MROWS * NSTATE];
__device__ __nv_bfloat16 g_Qhi[(size_t)MROWS * NSTATE];
__device__ __nv_bfloat16 g_Qlo[(size_t)MROWS * NSTATE];
__device__ __nv_bfloat16 g_Khi[(size_t)MROWS * NSTATE];
__device__ __nv_bfloat16 g_Klo[(size_t)MROWS * NSTATE];
__device__ __half        g_Vh [(size_t)MROWS * NSTATE];
__device__ __nv_bfloat16 g_Ohi[(size_t)MROWS * NSTATE];
__device__ __nv_bfloat16 g_Olo[(size_t)MROWS * NSTATE];
__device__ __nv_bfloat16 g_Whi[4][(size_t)NSTATE * NSTATE];
__device__ __nv_bfloat16 g_Wlo[4][(size_t)NSTATE * NSTATE];

__device__ __forceinline__ uint32_t smem_u32(const void* p) {
    uint32_t a;
    asm("{ .reg .u64 t; cvta.to.shared.u64 t, %1; cvt.u32.u64 %0, t; }"
        : "=r"(a) : "l"(p));
    return a;
}

#define LDSM_X4(r0, r1, r2, r3, addr)                                            \
    asm volatile("ldmatrix.sync.aligned.m8n8.x4.shared.b16 {%0,%1,%2,%3}, [%4];" \
                 : "=r"(r0), "=r"(r1), "=r"(r2), "=r"(r3) : "r"(addr))

#define LDSM_X4_T(r0, r1, r2, r3, addr)                                          \
    asm volatile("ldmatrix.sync.aligned.m8n8.x4.trans.shared.b16 {%0,%1,%2,%3}, [%4];" \
                 : "=r"(r0), "=r"(r1), "=r"(r2), "=r"(r3) : "r"(addr))

#define MMA_BF16(c0, c1, c2, c3, a0, a1, a2, a3, b0, b1)                         \
    asm volatile("mma.sync.aligned.m16n8k16.row.col.f32.bf16.bf16.f32 "          \
                 "{%0,%1,%2,%3}, {%4,%5,%6,%7}, {%8,%9}, {%0,%1,%2,%3};"         \
                 : "+f"(c0), "+f"(c1), "+f"(c2), "+f"(c3)                        \
                 : "r"(a0), "r"(a1), "r"(a2), "r"(a3), "r"(b0), "r"(b1))

#define MMA_F16(c0, c1, c2, c3, a0, a1, a2, a3, b0, b1)                          \
    asm volatile("mma.sync.aligned.m16n8k16.row.col.f32.f16.f16.f32 "            \
                 "{%0,%1,%2,%3}, {%4,%5,%6,%7}, {%8,%9}, {%0,%1,%2,%3};"         \
                 : "+f"(c0), "+f"(c1), "+f"(c2), "+f"(c3)                        \
                 : "r"(a0), "r"(a1), "r"(a2), "r"(a3), "r"(b0), "r"(b1))

#define PACK_H2(d, vlo, vhi)                                                     \
    asm("cvt.rn.f16x2.f32 %0, %1, %2;" : "=r"(d) : "f"(vhi), "f"(vlo))

#define CP16(dst, src, nbytes)                                                   \
    asm volatile("cp.async.cg.shared.global [%0], [%1], 16, %2;"                 \
                 :: "r"(dst), "l"(src), "r"(nbytes))
#define CP_COMMIT() asm volatile("cp.async.commit_group;" ::: "memory")
#define CP_WAIT1()  asm volatile("cp.async.wait_group 1;" ::: "memory")
#define CP_WAIT0()  asm volatile("cp.async.wait_group 0;" ::: "memory")

// ======================= split fp32 -> bf16 hi/lo ============================
__global__ __launch_bounds__(256) void split_bf16_kernel(
    const float* __restrict__ in0, const float* __restrict__ in1,
    const float* __restrict__ in2, const float* __restrict__ in3,
    __nv_bfloat16* __restrict__ hi, __nv_bfloat16* __restrict__ lo,
    size_t zstride, int n4)
{
    const int z = blockIdx.y;
    const float* in = (z == 0) ? in0 : (z == 1) ? in1 : (z == 2) ? in2 : in3;
    hi += z * zstride;
    lo += z * zstride;
    int i = blockIdx.x * blockDim.x + threadIdx.x;
    if (i < n4) {
        float4 v = *(const float4*)(in + (size_t)i * 4);
        __nv_bfloat16 hx = __float2bfloat16(v.x);
        __nv_bfloat16 hy = __float2bfloat16(v.y);
        __nv_bfloat16 hz = __float2bfloat16(v.z);
        __nv_bfloat16 hw = __float2bfloat16(v.w);
        __nv_bfloat162 h0 = {hx, hy}, h1 = {hz, hw};
        __nv_bfloat162 l0 = {__float2bfloat16(v.x - __bfloat162float(hx)),
                             __float2bfloat16(v.y - __bfloat162float(hy))};
        __nv_bfloat162 l1 = {__float2bfloat16(v.z - __bfloat162float(hz)),
                             __float2bfloat16(v.w - __bfloat162float(hw))};
        *(__nv_bfloat162*)(hi + (size_t)i * 4)     = h0;
        *(__nv_bfloat162*)(hi + (size_t)i * 4 + 2) = h1;
        *(__nv_bfloat162*)(lo + (size_t)i * 4)     = l0;
        *(__nv_bfloat162*)(lo + (size_t)i * 4 + 2) = l1;
    }
}

// ======== pipelined HMMA GEMM: C = (Ahi+Alo) @ (Bhi+Blo)^T + bias ============
// Double-buffered cp.async, CTA tile 128x128, BK=32, 8 warps (2x4), warp 64x32.
// PASS 0: grid.z in {0:Q->hilo(+bq), 1:K->hilo, 2:V->f16(+bv)}
// PASS 1: O gemm -> f32 (+bo)
#define GBK     32
#define GPAD    40
#define GK_ITERS (NSTATE / GBK)            // 32
#define ARR_B   (128 * GPAD * 2)           // 10240 bytes per array
#define STG_B   (4 * ARR_B)                // 40960 bytes per stage
#define GSMEM   (2 * STG_B)                // 81920 bytes

template <int PASS>
__global__ __launch_bounds__(256) void hmma_gemm_kernel(
    const __nv_bfloat16* __restrict__ Ahi, const __nv_bfloat16* __restrict__ Alo,
    const __nv_bfloat16* __restrict__ Wh,  const __nv_bfloat16* __restrict__ Wl,
    const float* __restrict__ bq, const float* __restrict__ bv,
    const float* __restrict__ bo,
    __nv_bfloat16* __restrict__ qhi, __nv_bfloat16* __restrict__ qlo,
    __nv_bfloat16* __restrict__ khi, __nv_bfloat16* __restrict__ klo,
    __half* __restrict__ vh, float* __restrict__ outf, int M)
{
    extern __shared__ __align__(16) char dsm[];
    const int z = (PASS == 0) ? blockIdx.z : 3;
    const __nv_bfloat16* Bhi = Wh + (size_t)z * NSTATE * NSTATE;
    const __nv_bfloat16* Blo = Wl + (size_t)z * NSTATE * NSTATE;
    const float* bias = (PASS == 1) ? bo : ((z == 0) ? bq : (z == 2) ? bv : nullptr);

    const int tid  = threadIdx.x;
    const int wid  = tid >> 5;
    const int lane = tid & 31;
    const int m0 = blockIdx.y * 128;
    const int n0 = blockIdx.x * 128;
    const int mbase = (wid >> 2) * 64;
    const int nbase = (wid & 3) * 32;

    const uint32_t uBase = smem_u32(dsm);

    float acc[4][4][4];
#pragma unroll
    for (int i = 0; i < 4; i++)
#pragma unroll
        for (int j = 0; j < 4; j++)
#pragma unroll
            for (int q = 0; q < 4; q++) acc[i][j][q] = 0.f;

    // loader indexing: 512 16B-chunks per array, 2 per thread
    const int lrow0 = (tid + 0)   >> 2, lc0 = (tid & 3) * 8;
    const int lrow1 = (tid + 256) >> 2;
    const int okA0 = (m0 + lrow0 < M) ? 16 : 0;
    const int okA1 = (m0 + lrow1 < M) ? 16 : 0;
    const size_t ga0 = (size_t)(m0 + lrow0) * NSTATE + lc0;
    const size_t ga1 = (size_t)(m0 + lrow1) * NSTATE + lc0;
    const size_t gb0 = (size_t)(n0 + lrow0) * NSTATE + lc0;
    const size_t gb1 = (size_t)(n0 + lrow1) * NSTATE + lc0;
    const uint32_t so0 = (uint32_t)(lrow0 * GPAD + lc0) * 2;
    const uint32_t so1 = (uint32_t)(lrow1 * GPAD + lc0) * 2;

#define ISSUE_CHUNK(kit, stg) do {                                               \
        const int k0_ = (kit) * GBK;                                             \
        const uint32_t sb = uBase + (stg) * STG_B;                               \
        CP16(sb + 0 * ARR_B + so0, Ahi + ga0 + k0_, okA0);                       \
        CP16(sb + 0 * ARR_B + so1, Ahi + ga1 + k0_, okA1);                       \
        CP16(sb + 1 * ARR_B + so0, Alo + ga0 + k0_, okA0);                       \
        CP16(sb + 1 * ARR_B + so1, Alo + ga1 + k0_, okA1);                       \
        CP16(sb + 2 * ARR_B + so0, Bhi + gb0 + k0_, 16);                         \
        CP16(sb + 2 * ARR_B + so1, Bhi + gb1 + k0_, 16);                         \
        CP16(sb + 3 * ARR_B + so0, Blo + gb0 + k0_, 16);                         \
        CP16(sb + 3 * ARR_B + so1, Blo + gb1 + k0_, 16);                         \
        CP_COMMIT();                                                             \
    } while (0)

    ISSUE_CHUNK(0, 0);

    const int aRow = lane & 15, aKof = (lane >> 4) * 8;
    const int bNof = ((lane >> 4) * 8) + (lane & 7);
    const int bKof = ((lane >> 3) & 1) * 8;

    for (int kit = 0; kit < GK_ITERS; kit++) {
        if (kit + 1 < GK_ITERS) { ISSUE_CHUNK(kit + 1, (kit + 1) & 1); CP_WAIT1(); }
        else                    { CP_WAIT0(); }
        __syncthreads();

        const uint32_t sb = uBase + (kit & 1) * STG_B;
        const uint32_t uAh = sb, uAl = sb + ARR_B, uBh = sb + 2 * ARR_B,
                       uBl = sb + 3 * ARR_B;
#pragma unroll
        for (int ks = 0; ks < 2; ks++) {
            const int kof = ks * 16;
            uint32_t ah[4][4], al[4][4];
#pragma unroll
            for (int mt = 0; mt < 4; mt++) {
                const uint32_t off =
                    (uint32_t)((mbase + mt * 16 + aRow) * GPAD + kof + aKof) * 2;
                LDSM_X4(ah[mt][0], ah[mt][1], ah[mt][2], ah[mt][3], uAh + off);
                LDSM_X4(al[mt][0], al[mt][1], al[mt][2], al[mt][3], uAl + off);
            }
            uint32_t bh[4][2], bl[4][2];
#pragma unroll
            for (int np = 0; np < 2; np++) {
                const uint32_t off =
                    (uint32_t)((nbase + np * 16 + bNof) * GPAD + kof + bKof) * 2;
                LDSM_X4(bh[np * 2][0], bh[np * 2][1], bh[np * 2 + 1][0], bh[np * 2 + 1][1],
                        uBh + off);
                LDSM_X4(bl[np * 2][0], bl[np * 2][1], bl[np * 2 + 1][0], bl[np * 2 + 1][1],
                        uBl + off);
            }
#pragma unroll
            for (int mt = 0; mt < 4; mt++)
#pragma unroll
                for (int nt = 0; nt < 4; nt++) {
                    float* c4 = acc[mt][nt];
                    MMA_BF16(c4[0], c4[1], c4[2], c4[3],
                             ah[mt][0], ah[mt][1], ah[mt][2], ah[mt][3],
                             bh[nt][0], bh[nt][1]);
                    MMA_BF16(c4[0], c4[1], c4[2], c4[3],
                             ah[mt][0], ah[mt][1], ah[mt][2], ah[mt][3],
                             bl[nt][0], bl[nt][1]);
                    MMA_BF16(c4[0], c4[1], c4[2], c4[3],
                             al[mt][0], al[mt][1], al[mt][2], al[mt][3],
                             bh[nt][0], bh[nt][1]);
                }
        }
        __syncthreads();
    }
#undef ISSUE_CHUNK

    const int lr = lane >> 2;
    const int lc = (lane & 3) * 2;
#pragma unroll
    for (int mt = 0; mt < 4; mt++) {
#pragma unroll
        for (int half_ = 0; half_ < 2; half_++) {
            const int gm = m0 + mbase + mt * 16 + half_ * 8 + lr;
            if (gm < M) {
#pragma unroll
                for (int nt = 0; nt < 4; nt++) {
                    const int gn = n0 + nbase + nt * 8 + lc;
                    float vx = acc[mt][nt][half_ * 2 + 0];
                    float vy = acc[mt][nt][half_ * 2 + 1];
                    if (bias) { vx += bias[gn]; vy += bias[gn + 1]; }
                    const size_t idx = (size_t)gm * NSTATE + gn;
                    if (PASS == 1) {
                        *(float2*)(outf + idx) = make_float2(vx, vy);
                    } else if (z == 2) {
                        __half2 hv = {__float2half_rn(vx), __float2half_rn(vy)};
                        *(__half2*)(vh + idx) = hv;
                    } else {
                        __nv_bfloat16 hx = __float2bfloat16(vx);
                        __nv_bfloat16 hy = __float2bfloat16(vy);
                        __nv_bfloat162 h = {hx, hy};
                        __nv_bfloat162 l = {__float2bfloat16(vx - __bfloat162float(hx)),
                                            __float2bfloat16(vy - __bfloat162float(hy))};
                        if (z == 0) {
                            *(__nv_bfloat162*)(qhi + idx) = h;
                            *(__nv_bfloat162*)(qlo + idx) = l;
                        } else {
                            *(__nv_bfloat162*)(khi + idx) = h;
                            *(__nv_bfloat162*)(klo + idx) = l;
                        }
                    }
                }
            }
        }
    }
}

// ================= HMMA flash attention (causal) =============================
#define AQ    128
#define AKV   64
#define APAD  72

__global__ __launch_bounds__(256) void flash_hmma_kernel(
    const __nv_bfloat16* __restrict__ Qhi, const __nv_bfloat16* __restrict__ Qlo,
    const __nv_bfloat16* __restrict__ Khi, const __nv_bfloat16* __restrict__ Klo,
    const __half* __restrict__ Vh,
    __nv_bfloat16* __restrict__ Ohi, __nv_bfloat16* __restrict__ Olo)
{
    __shared__ __align__(16) __nv_bfloat16 sH[AQ * APAD];
    __shared__ __align__(16) __nv_bfloat16 sL[AQ * APAD];
    __shared__ __align__(16) __half        sV[AKV * APAD];

    const int tid  = threadIdx.x;
    const int wid  = tid >> 5;
    const int lane = tid & 31;
    const int bh = blockIdx.y;
    const int b  = bh >> 4;
    const int h  = bh & 15;
    const int q0 = blockIdx.x * AQ;
    const size_t rowBase = (size_t)b * SLEN;
    const int colOff = h * HDIM;

    const uint32_t uH = smem_u32(sH), uL = smem_u32(sL), uV = smem_u32(sV);

#pragma unroll
    for (int it = 0; it < 4; it++) {
        const int id = tid + it * 256;
        const int r  = id >> 3;
        const int c  = id & 7;
        const int gq = q0 + r;
        uint4 vh = make_uint4(0, 0, 0, 0), vl = make_uint4(0, 0, 0, 0);
        if (gq < SLEN) {
            const size_t off = (rowBase + gq) * NSTATE + colOff + c * 8;
            vh = *(const uint4*)(Qhi + off);
            vl = *(const uint4*)(Qlo + off);
        }
        *(uint4*)(sH + r * APAD + c * 8) = vh;
        *(uint4*)(sL + r * APAD + c * 8) = vl;
    }
    __syncthreads();

    const int aRow = lane & 15, aKof = (lane >> 4) * 8;
    const int wq0 = wid * 16;
    uint32_t qh[4][4], ql[4][4];
#pragma unroll
    for (int ks = 0; ks < 4; ks++) {
        const uint32_t off = (uint32_t)((wq0 + aRow) * APAD + ks * 16 + aKof) * 2;
        LDSM_X4(qh[ks][0], qh[ks][1], qh[ks][2], qh[ks][3], uH + off);
        LDSM_X4(ql[ks][0], ql[ks][1], ql[ks][2], ql[ks][3], uL + off);
    }
    __syncthreads();

    const int gqa = q0 + wq0 + (lane >> 2);
    float mr0 = -1e30f, mr1 = -1e30f, l0 = 0.f, l1 = 0.f;
    float oacc[8][4];
#pragma unroll
    for (int i = 0; i < 8; i++)
#pragma unroll
        for (int q = 0; q < 4; q++) oacc[i][q] = 0.f;

    const int bNof = ((lane >> 4) * 8) + (lane & 7);
    const int bKof = ((lane >> 3) & 1) * 8;
    const int vRow = ((lane >> 3) & 1) * 8 + (lane & 7);
    const int vCof = (lane >> 4) * 8;

    const int tEnd = min(q0 + AQ - 1, SLEN - 1) / AKV;
    for (int t = 0; t <= tEnd; t++) {
        const int j0 = t * AKV;
#pragma unroll
        for (int it = 0; it < 2; it++) {
            const int id = tid + it * 256;
            const int r  = id >> 3;
            const int c  = id & 7;
            const int gk = j0 + r;
            uint4 vh = make_uint4(0, 0, 0, 0), vl = make_uint4(0, 0, 0, 0),
                  vv = make_uint4(0, 0, 0, 0);
            if (gk < SLEN) {
                const size_t off = (rowBase + gk) * NSTATE + colOff + c * 8;
                vh = *(const uint4*)(Khi + off);
                vl = *(const uint4*)(Klo + off);
                vv = *(const uint4*)(Vh + off);
            }
            *(uint4*)(sH + r * APAD + c * 8) = vh;
            *(uint4*)(sL + r * APAD + c * 8) = vl;
            *(uint4*)(sV + r * APAD + c * 8) = vv;
        }
        __syncthreads();

        if (j0 <= q0 + wq0 + 15) {
            float S[8][4];
#pragma unroll
            for (int nt = 0; nt < 8; nt++)
#pragma unroll
                for (int q = 0; q < 4; q++) S[nt][q] = 0.f;
#pragma unroll
            for (int ks = 0; ks < 4; ks++) {
                uint32_t kh[8][2], kl[8][2];
#pragma unroll
                for (int np = 0; np < 4; np++) {
                    const uint32_t off =
                        (uint32_t)((np * 16 + bNof) * APAD + ks * 16 + bKof) * 2;
                    LDSM_X4(kh[np * 2][0], kh[np * 2][1],
                            kh[np * 2 + 1][0], kh[np * 2 + 1][1], uH + off);
                    LDSM_X4(kl[np * 2][0], kl[np * 2][1],
                            kl[np * 2 + 1][0], kl[np * 2 + 1][1], uL + off);
                }
#pragma unroll
                for (int nt = 0; nt < 8; nt++) {
                    MMA_BF16(S[nt][0], S[nt][1], S[nt][2], S[nt][3],
                             qh[ks][0], qh[ks][1], qh[ks][2], qh[ks][3],
                             kh[nt][0], kh[nt][1]);
                    MMA_BF16(S[nt][0], S[nt][1], S[nt][2], S[nt][3],
                             qh[ks][0], qh[ks][1], qh[ks][2], qh[ks][3],
                             kl[nt][0], kl[nt][1]);
                    MMA_BF16(S[nt][0], S[nt][1], S[nt][2], S[nt][3],
                             ql[ks][0], ql[ks][1], ql[ks][2], ql[ks][3],
                             kh[nt][0], kh[nt][1]);
                }
            }
            float mx0 = mr0, mx1 = mr1;
            const int jc = j0 + 2 * (lane & 3);
#pragma unroll
            for (int nt = 0; nt < 8; nt++) {
#pragma unroll
                for (int q = 0; q < 4; q++) {
                    const int jg  = jc + nt * 8 + (q & 1);
                    const int row = (q < 2) ? gqa : gqa + 8;
                    const bool ok = (jg <= row) && (jg < SLEN);
                    const float sv = ok ? S[nt][q] * 0.125f : -1e30f;
                    S[nt][q] = sv;
                    if (q < 2) mx0 = fmaxf(mx0, sv); else mx1 = fmaxf(mx1, sv);
                }
            }
            mx0 = fmaxf(mx0, __shfl_xor_sync(0xffffffffu, mx0, 1));
            mx0 = fmaxf(mx0, __shfl_xor_sync(0xffffffffu, mx0, 2));
            mx1 = fmaxf(mx1, __shfl_xor_sync(0xffffffffu, mx1, 1));
            mx1 = fmaxf(mx1, __shfl_xor_sync(0xffffffffu, mx1, 2));
            const float corr0 = __expf(mr0 - mx0);
            const float corr1 = __expf(mr1 - mx1);
            mr0 = mx0; mr1 = mx1;
            float ps0 = 0.f, ps1 = 0.f;
#pragma unroll
            for (int nt = 0; nt < 8; nt++) {
#pragma unroll
                for (int q = 0; q < 4; q++) {
                    const float p = __expf(S[nt][q] - ((q < 2) ? mx0 : mx1));
                    S[nt][q] = p;
                    if (q < 2) ps0 += p; else ps1 += p;
                }
            }
            ps0 += __shfl_xor_sync(0xffffffffu, ps0, 1);
            ps0 += __shfl_xor_sync(0xffffffffu, ps0, 2);
            ps1 += __shfl_xor_sync(0xffffffffu, ps1, 1);
            ps1 += __shfl_xor_sync(0xffffffffu, ps1, 2);
            l0 = l0 * corr0 + ps0;
            l1 = l1 * corr1 + ps1;
#pragma unroll
            for (int nt = 0; nt < 8; nt++) {
                oacc[nt][0] *= corr0; oacc[nt][1] *= corr0;
                oacc[nt][2] *= corr1; oacc[nt][3] *= corr1;
            }
#pragma unroll
            for (int ks2 = 0; ks2 < 4; ks2++) {
                uint32_t a0, a1, a2, a3;
                PACK_H2(a0, S[2 * ks2][0],     S[2 * ks2][1]);
                PACK_H2(a1, S[2 * ks2][2],     S[2 * ks2][3]);
                PACK_H2(a2, S[2 * ks2 + 1][0], S[2 * ks2 + 1][1]);
                PACK_H2(a3, S[2 * ks2 + 1][2], S[2 * ks2 + 1][3]);
#pragma unroll
                for (int dp = 0; dp < 4; dp++) {
                    uint32_t v0, v1, v2, v3;
                    const uint32_t off =
                        (uint32_t)((ks2 * 16 + vRow) * APAD + dp * 16 + vCof) * 2;
                    LDSM_X4_T(v0, v1, v2, v3, uV + off);
                    MMA_F16(oacc[2 * dp][0], oacc[2 * dp][1],
                            oacc[2 * dp][2], oacc[2 * dp][3],
                            a0, a1, a2, a3, v0, v1);
                    MMA_F16(oacc[2 * dp + 1][0], oacc[2 * dp + 1][1],
                            oacc[2 * dp + 1][2], oacc[2 * dp + 1][3],
                            a0, a1, a2, a3, v2, v3);
                }
            }
        }
        __syncthreads();
    }

    const float inv0 = (l0 > 0.f) ? 1.f / l0 : 0.f;
    const float inv1 = (l1 > 0.f) ? 1.f / l1 : 0.f;
#pragma unroll
    for (int nt = 0; nt < 8; nt++) {
        const int d = colOff + nt * 8 + 2 * (lane & 3);
        if (gqa < SLEN) {
            const float vx = oacc[nt][0] * inv0;
            const float vy = oacc[nt][1] * inv0;
            __nv_bfloat16 hx = __float2bfloat16(vx), hy = __float2bfloat16(vy);
            __nv_bfloat162 hh = {hx, hy};
            __nv_bfloat162 ll = {__float2bfloat16(vx - __bfloat162float(hx)),
                                 __float2bfloat16(vy - __bfloat162float(hy))};
            const size_t idx = (rowBase + gqa) * NSTATE + d;
            *(__nv_bfloat162*)(Ohi + idx) = hh;
            *(__nv_bfloat162*)(Olo + idx) = ll;
        }
        if (gqa + 8 < SLEN) {
            const float vx = oacc[nt][2] * inv1;
            const float vy = oacc[nt][3] * inv1;
            __nv_bfloat16 hx = __float2bfloat16(vx), hy = __float2bfloat16(vy);
            __nv_bfloat162 hh = {hx, hy};
            __nv_bfloat162 ll = {__float2bfloat16(vx - __bfloat162float(hx)),
                                 __float2bfloat16(vy - __bfloat162float(hy))};
            const size_t idx = (rowBase + gqa + 8) * NSTATE + d;
            *(__nv_bfloat162*)(Ohi + idx) = hh;
            *(__nv_bfloat162*)(Olo + idx) = ll;
        }
    }
}

// ---------------- launch -----------------------------------------------------
extern "C" void kernel_launch(void* const* d_in, const int* in_sizes, int n_in,
                              void* d_out, int out_size)
{
    const float* x  = (const float*)d_in[0];
    const float* Wq = (const float*)d_in[2];
    const float* bq = (const float*)d_in[3];
    const float* Wk = (const float*)d_in[4];
    const float* Wv = (const float*)d_in[5];
    const float* bv = (const float*)d_in[6];
    const float* Wo = (const float*)d_in[7];
    const float* bo = (const float*)d_in[8];
    float* out = (float*)d_out;

    __nv_bfloat16 *xhi, *xlo, *qhi, *qlo, *khi, *klo, *ohi, *olo, *whi, *wlo;
    __half* vh;
    cudaGetSymbolAddress((void**)&xhi, g_Xhi);
    cudaGetSymbolAddress((void**)&xlo, g_Xlo);
    cudaGetSymbolAddress((void**)&qhi, g_Qhi);
    cudaGetSymbolAddress((void**)&qlo, g_Qlo);
    cudaGetSymbolAddress((void**)&khi, g_Khi);
    cudaGetSymbolAddress((void**)&klo, g_Klo);
    cudaGetSymbolAddress((void**)&vh,  g_Vh);
    cudaGetSymbolAddress((void**)&ohi, g_Ohi);
    cudaGetSymbolAddress((void**)&olo, g_Olo);
    cudaGetSymbolAddress((void**)&whi, g_Whi);
    cudaGetSymbolAddress((void**)&wlo, g_Wlo);
    const size_t WSZ = (size_t)NSTATE * NSTATE;

    cudaFuncSetAttribute(hmma_gemm_kernel<0>,
                         cudaFuncAttributeMaxDynamicSharedMemorySize, GSMEM);
    cudaFuncSetAttribute(hmma_gemm_kernel<1>,
                         cudaFuncAttributeMaxDynamicSharedMemorySize, GSMEM);

    const int xn4 = MROWS * NSTATE / 4;
    const int wn4 = NSTATE * NSTATE / 4;
    // x split
    split_bf16_kernel<<<dim3((xn4 + 255) / 256, 1), 256>>>(
        x, nullptr, nullptr, nullptr, xhi, xlo, 0, xn4);
    // 4 weight splits in one launch
    split_bf16_kernel<<<dim3((wn4 + 255) / 256, 4), 256>>>(
        Wq, Wk, Wv, Wo, whi, wlo, WSZ, wn4);

    // fused Q/K/V projections
    const dim3 qkvgrid(NSTATE / 128, (MROWS + 127) / 128, 3);
    hmma_gemm_kernel<0><<<qkvgrid, 256, GSMEM>>>(
        xhi, xlo, whi, wlo, bq, bv, bo, qhi, qlo, khi, klo, vh, nullptr, MROWS);

    const dim3 agrid((SLEN + AQ - 1) / AQ, BATCH * NHEAD);
    flash_hmma_kernel<<<agrid, 256>>>(qhi, qlo, khi, klo, vh, ohi, olo);

    const dim3 ogrid(NSTATE / 128, (MROWS + 127) / 128, 1);
    hmma_gemm_kernel<1><<<ogrid, 256, GSMEM>>>(
        ohi, olo, whi, wlo, bq, bv, bo, nullptr, nullptr, nullptr, nullptr, vh, out, MROWS);
}